// round 1
// baseline (speedup 1.0000x reference)
#include <cuda_runtime.h>

#define NROWS 8192
#define C     128      // C_IN = C_OUT
#define KSPLIT 8
#define KRANGE (NROWS / KSPLIT)   // 1024
#define BM 128
#define BK 32
#define TM 8
#define TN 8
#define THREADS 256

// Scratch (no allocations allowed): h = x@W^T, and K-split partial sums.
__device__ float g_h[NROWS * C];                 // 4 MB
__device__ float g_part[KSPLIT * NROWS * C];     // 32 MB

// ---------------------------------------------------------------------------
// Kernel 1: h[n,o] = sum_c x[n,c] * W[o,c]
// Block: 128 threads (one per o), handles 16 rows of x.
// ---------------------------------------------------------------------------
__global__ void k_linear(const float* __restrict__ x, const float* __restrict__ W) {
    __shared__ float xs[16][C];
    const int n0  = blockIdx.x * 16;
    const int tid = threadIdx.x;   // 0..127 == output channel o

    #pragma unroll
    for (int r = 0; r < 16; r++)
        xs[r][tid] = x[(size_t)(n0 + r) * C + tid];
    __syncthreads();

    const int o = tid;
    const float* __restrict__ w = W + (size_t)o * C;

    float acc[16];
    #pragma unroll
    for (int r = 0; r < 16; r++) acc[r] = 0.0f;

    #pragma unroll 4
    for (int c = 0; c < C; c++) {
        const float wv = w[c];
        #pragma unroll
        for (int r = 0; r < 16; r++) acc[r] += xs[r][c] * wv;   // xs: smem broadcast
    }

    #pragma unroll
    for (int r = 0; r < 16; r++)
        g_h[(size_t)(n0 + r) * C + o] = acc[r];
}

// ---------------------------------------------------------------------------
// Kernel 2: part[s] += (adj .* mask)[i0:i0+BM, Kslice_s] @ h[Kslice_s, :]
// grid = (NROWS/BM, KSPLIT), block = 256 threads, 8x8 register microtile.
// ---------------------------------------------------------------------------
__global__ void __launch_bounds__(THREADS, 2)
k_spmm(const float* __restrict__ adj, const float* __restrict__ mask) {
    __shared__ float a_sm[BM][BK + 1];   // (adj*mask) tile, [row][k], +1 pad
    __shared__ float b_sm[BK][C + 4];    // h tile, [k][col], +4 pad

    const int i0  = blockIdx.x * BM;
    const int k0  = blockIdx.y * KRANGE;
    const int tid = threadIdx.x;
    const int ti  = tid >> 4;            // 0..15 -> rows ti*8..ti*8+7
    const int tj  = tid & 15;            // 0..15 -> cols tj*8..tj*8+7

    // b-loader mapping: row = tid/8 (0..31), col base = (tid%8)*16
    const int br = tid >> 3;
    const int bc = (tid & 7) * 16;

    float acc[TM][TN];
    #pragma unroll
    for (int r = 0; r < TM; r++)
        #pragma unroll
        for (int c = 0; c < TN; c++) acc[r][c] = 0.0f;

    for (int kb = 0; kb < KRANGE; kb += BK) {
        const int k = k0 + kb;

        // --- load A tile: 128 rows x 32 k of adj*mask (4 float4 per thread) ---
        #pragma unroll
        for (int j = 0; j < 4; j++) {
            const int f  = tid + THREADS * j;   // 0..1023
            const int ia = f >> 3;              // 0..127
            const int kq = (f & 7) * 4;         // 0..28
            const size_t goff = (size_t)(i0 + ia) * NROWS + (size_t)(k + kq);
            const float4 av = *(const float4*)(adj  + goff);
            const float4 mv = *(const float4*)(mask + goff);
            a_sm[ia][kq + 0] = av.x * mv.x;
            a_sm[ia][kq + 1] = av.y * mv.y;
            a_sm[ia][kq + 2] = av.z * mv.z;
            a_sm[ia][kq + 3] = av.w * mv.w;
        }

        // --- load B tile: 32 rows x 128 cols of h (4 float4 per thread) ---
        {
            const float* __restrict__ src = g_h + (size_t)(k + br) * C + bc;
            #pragma unroll
            for (int j = 0; j < 4; j++) {
                const float4 v = *(const float4*)(src + j * 4);
                *(float4*)&b_sm[br][bc + j * 4] = v;
            }
        }
        __syncthreads();

        // --- 8x8 microtile FMA over BK ---
        #pragma unroll
        for (int kk = 0; kk < BK; kk++) {
            float af[TM], bf[TN];
            #pragma unroll
            for (int r = 0; r < TM; r++) af[r] = a_sm[ti * TM + r][kk];  // broadcast
            #pragma unroll
            for (int c4 = 0; c4 < TN; c4 += 4) {
                const float4 v = *(const float4*)&b_sm[kk][tj * TN + c4];
                bf[c4 + 0] = v.x; bf[c4 + 1] = v.y; bf[c4 + 2] = v.z; bf[c4 + 3] = v.w;
            }
            #pragma unroll
            for (int r = 0; r < TM; r++)
                #pragma unroll
                for (int c = 0; c < TN; c++)
                    acc[r][c] += af[r] * bf[c];
        }
        __syncthreads();
    }

    // --- store partial sums ---
    float* __restrict__ dst = g_part + ((size_t)blockIdx.y * NROWS + i0) * C;
    #pragma unroll
    for (int r = 0; r < TM; r++) {
        const int row = ti * TM + r;
        #pragma unroll
        for (int c4 = 0; c4 < TN; c4 += 4) {
            float4 v;
            v.x = acc[r][c4 + 0];
            v.y = acc[r][c4 + 1];
            v.z = acc[r][c4 + 2];
            v.w = acc[r][c4 + 3];
            *(float4*)(dst + (size_t)row * C + tj * TN + c4) = v;
        }
    }
}

// ---------------------------------------------------------------------------
// Kernel 3: out = sum_s part[s] + h   (the +h term implements adj_eff's +I)
// ---------------------------------------------------------------------------
__global__ void k_reduce(float* __restrict__ out) {
    const size_t idx = (size_t)blockIdx.x * blockDim.x + threadIdx.x;
    float s = g_h[idx];
    #pragma unroll
    for (int p = 0; p < KSPLIT; p++)
        s += g_part[(size_t)p * (NROWS * C) + idx];
    out[idx] = s;
}

// ---------------------------------------------------------------------------
extern "C" void kernel_launch(void* const* d_in, const int* in_sizes, int n_in,
                              void* d_out, int out_size) {
    const float* x    = (const float*)d_in[0];
    const float* adj  = (const float*)d_in[1];
    const float* mask = (const float*)d_in[2];
    const float* W    = (const float*)d_in[3];
    float* out = (float*)d_out;

    k_linear<<<NROWS / 16, 128>>>(x, W);

    dim3 g2(NROWS / BM, KSPLIT);
    k_spmm<<<g2, THREADS>>>(adj, mask);

    k_reduce<<<(NROWS * C) / 256, 256>>>(out);
}

// round 3
// speedup vs baseline: 2.3134x; 2.3134x over previous
#include <cuda_runtime.h>
#include <cuda_bf16.h>
#include <cstdint>

#define NROWS 8192
#define C     128
#define KSPLIT 8
#define KRANGE (NROWS / KSPLIT)   // 1024
#define BK 32
#define NITER (KRANGE / BK)       // 32
#define BM 128
#define THREADS 256

// row stride in smem tiles: 32 bf16 = 64B, padded to 80B (conflict-free ldmatrix)
#define RSTRIDE 80
#define TILE_B (128 * RSTRIDE)    // 10240 bytes per tile
#define STAGE  (4 * TILE_B)       // A_hi, A_lo, B_hi, B_lo
#define OFF_AH 0
#define OFF_AL TILE_B
#define OFF_BH (2 * TILE_B)
#define OFF_BL (3 * TILE_B)
#define SMEM_BYTES (2 * STAGE + 256)

// ---- scratch ----
__device__ float g_h[NROWS * C];                       // h row-major (for +I)
__device__ __nv_bfloat16 g_hT_hi[C * NROWS];           // h^T hi, [o][node]
__device__ __nv_bfloat16 g_hT_lo[C * NROWS];           // h^T lo
__device__ float g_part[KSPLIT * NROWS * C];

// ============================ helpers ============================
__device__ __forceinline__ uint32_t smem_u32(const void* p) {
    uint32_t a;
    asm("{ .reg .u64 t; cvta.to.shared.u64 t, %1; cvt.u32.u64 %0, t; }" : "=r"(a) : "l"(p));
    return a;
}
__device__ __forceinline__ void ldsm4(uint32_t* r, uint32_t addr) {
    asm volatile("ldmatrix.sync.aligned.m8n8.x4.shared.b16 {%0,%1,%2,%3}, [%4];"
                 : "=r"(r[0]), "=r"(r[1]), "=r"(r[2]), "=r"(r[3]) : "r"(addr));
}
__device__ __forceinline__ void ldsm2(uint32_t* r, uint32_t addr) {
    asm volatile("ldmatrix.sync.aligned.m8n8.x2.shared.b16 {%0,%1}, [%2];"
                 : "=r"(r[0]), "=r"(r[1]) : "r"(addr));
}
__device__ __forceinline__ void mma_bf16(float* d, const uint32_t* a, const uint32_t* b) {
    asm volatile(
        "mma.sync.aligned.m16n8k16.row.col.f32.bf16.bf16.f32 "
        "{%0,%1,%2,%3}, {%4,%5,%6,%7}, {%8,%9}, {%0,%1,%2,%3};"
        : "+f"(d[0]), "+f"(d[1]), "+f"(d[2]), "+f"(d[3])
        : "r"(a[0]), "r"(a[1]), "r"(a[2]), "r"(a[3]), "r"(b[0]), "r"(b[1]));
}
__device__ __forceinline__ void cp16(uint32_t dst, const void* src) {
    asm volatile("cp.async.cg.shared.global [%0], [%1], 16;" :: "r"(dst), "l"(src) : "memory");
}
#define CP_COMMIT() asm volatile("cp.async.commit_group;" ::: "memory")
#define CP_WAIT0()  asm volatile("cp.async.wait_group 0;" ::: "memory")

__device__ __forceinline__ uint32_t pack_bf2(float lo_el, float hi_el) {
    __nv_bfloat162 t = __floats2bfloat162_rn(lo_el, hi_el);   // .x = first = low half
    return *reinterpret_cast<uint32_t*>(&t);
}
__device__ __forceinline__ float bf_hi(float v) {
    return __bfloat162float(__float2bfloat16_rn(v));
}

// ============================ Kernel 1: linear + bf16 split transpose ============================
__global__ void __launch_bounds__(256) k_linear(const float* __restrict__ x,
                                                const float* __restrict__ W) {
    __shared__ float xs[16][C];
    __shared__ float tp[C][12];
    const int tid = threadIdx.x;
    const int n0 = blockIdx.x * 16;

    #pragma unroll
    for (int i = tid; i < 16 * C / 4; i += 256) {
        int r = i >> 5, c4 = (i & 31) * 4;
        *(float4*)&xs[r][c4] = *(const float4*)(x + (size_t)(n0 + r) * C + c4);
    }
    __syncthreads();

    const int o = tid & 127, rh = tid >> 7;
    const float4* __restrict__ w4 = (const float4*)(W + (size_t)o * C);

    float acc[8];
    #pragma unroll
    for (int r = 0; r < 8; r++) acc[r] = 0.0f;

    #pragma unroll 8
    for (int c4 = 0; c4 < 32; c4++) {
        const float4 wv = w4[c4];
        #pragma unroll
        for (int r = 0; r < 8; r++) {
            const float4 xv = *(const float4*)&xs[rh * 8 + r][c4 * 4];
            acc[r] += xv.x * wv.x;
            acc[r] += xv.y * wv.y;
            acc[r] += xv.z * wv.z;
            acc[r] += xv.w * wv.w;
        }
    }

    #pragma unroll
    for (int r = 0; r < 8; r++)
        g_h[(size_t)(n0 + rh * 8 + r) * C + o] = acc[r];

    // transpose + bf16 hi/lo: 4 passes (row-half x hi/lo)
    #pragma unroll
    for (int pass = 0; pass < 4; pass++) {
        const int prh = pass >> 1;
        const bool dohi = !(pass & 1);
        __syncthreads();
        if (rh == prh) {
            #pragma unroll
            for (int r = 0; r < 8; r++) {
                float v = acc[r];
                tp[o][r] = dohi ? v : (v - bf_hi(v));
            }
        }
        __syncthreads();
        {
            const int oo = tid >> 1, q = tid & 1;
            float4 v = *(float4*)&tp[oo][q * 4];
            uint2 pk;
            pk.x = pack_bf2(v.x, v.y);
            pk.y = pack_bf2(v.z, v.w);
            __nv_bfloat16* dst = (dohi ? g_hT_hi : g_hT_lo) +
                                 (size_t)oo * NROWS + n0 + prh * 8 + q * 4;
            *(uint2*)dst = pk;
        }
    }
}

// ============================ Kernel 2: 3xbf16 mma.sync SpMM ============================
__global__ void __launch_bounds__(THREADS, 1)
k_spmm(const float* __restrict__ adj, const float* __restrict__ mask) {
    extern __shared__ char smem[];
    const uint32_t sb = (smem_u32(smem) + 127) & ~127u;
    char* smc = smem + (sb - smem_u32(smem));

    const int tid = threadIdx.x, wid = tid >> 5, lid = tid & 31;
    const int i0 = blockIdx.x * BM;
    const int k0 = blockIdx.y * KRANGE;

    // ---- A (adj*mask) register-prefetch mapping: 4 slots/thread ----
    const int r0  = tid >> 3;            // 0..31 (+32j)
    const int kq  = (tid & 7) * 4;       // 0..28
    const float* pa = adj  + (size_t)(i0 + r0) * NROWS + k0 + kq;
    const float* pm = mask + (size_t)(i0 + r0) * NROWS + k0 + kq;
    // smem store offsets (bytes, within tile)
    uint32_t aso[4];
    #pragma unroll
    for (int j = 0; j < 4; j++) aso[j] = (uint32_t)((r0 + 32 * j) * RSTRIDE + kq * 2);

    // ---- B cp.async mapping: 2 slots/thread ----
    const int bo  = tid >> 2;            // 0..63 (+64j)
    const int bkb = (tid & 3) * 8;       // element offset 0..24
    const __nv_bfloat16* pbh = g_hT_hi + (size_t)bo * NROWS + k0 + bkb;
    const __nv_bfloat16* pbl = g_hT_lo + (size_t)bo * NROWS + k0 + bkb;
    uint32_t bso[2];
    #pragma unroll
    for (int j = 0; j < 2; j++) bso[j] = (uint32_t)((bo + 64 * j) * RSTRIDE + bkb * 2);

    // ---- warp tile mapping ----
    const int m_base = (wid & 1) * 64;
    const int n_base = (wid >> 1) * 32;
    const uint32_t lane_off_A = (uint32_t)((lid & 15) * RSTRIDE + ((lid >> 4) << 4));
    const uint32_t lane_off_B = (uint32_t)((lid & 7) * RSTRIDE + (((lid >> 3) & 1) << 4));

    float acc[4][4][4];
    #pragma unroll
    for (int m = 0; m < 4; m++)
        #pragma unroll
        for (int n = 0; n < 4; n++)
            #pragma unroll
            for (int q = 0; q < 4; q++) acc[m][n][q] = 0.0f;

    float4 va[4], vm[4];

    // ---------- prologue: iter 0 ----------
    #pragma unroll
    for (int j = 0; j < 4; j++) {
        va[j] = *(const float4*)(pa + (size_t)32 * j * NROWS);
        vm[j] = *(const float4*)(pm + (size_t)32 * j * NROWS);
    }
    cp16(sb + OFF_BH + bso[0], pbh);
    cp16(sb + OFF_BH + bso[1], pbh + (size_t)64 * NROWS);
    cp16(sb + OFF_BL + bso[0], pbl);
    cp16(sb + OFF_BL + bso[1], pbl + (size_t)64 * NROWS);
    CP_COMMIT();
    #pragma unroll
    for (int j = 0; j < 4; j++) {
        float4 p;
        p.x = va[j].x * vm[j].x; p.y = va[j].y * vm[j].y;
        p.z = va[j].z * vm[j].z; p.w = va[j].w * vm[j].w;
        float hx = bf_hi(p.x), hy = bf_hi(p.y), hz = bf_hi(p.z), hw = bf_hi(p.w);
        uint2 hi, lo;
        hi.x = pack_bf2(p.x, p.y);           hi.y = pack_bf2(p.z, p.w);
        lo.x = pack_bf2(p.x - hx, p.y - hy); lo.y = pack_bf2(p.z - hz, p.w - hw);
        *(uint2*)(smc + OFF_AH + aso[j]) = hi;
        *(uint2*)(smc + OFF_AL + aso[j]) = lo;
    }
    // prefetch iter 1 (A)
    #pragma unroll
    for (int j = 0; j < 4; j++) {
        va[j] = *(const float4*)(pa + (size_t)32 * j * NROWS + BK);
        vm[j] = *(const float4*)(pm + (size_t)32 * j * NROWS + BK);
    }
    CP_WAIT0();
    __syncthreads();

    // ---------- mainloop ----------
    #pragma unroll 1
    for (int it = 0; it < NITER; it++) {
        const uint32_t cur = (uint32_t)(it & 1) * STAGE;
        const uint32_t nxt = (uint32_t)((it + 1) & 1) * STAGE;

        if (it + 1 < NITER) {
            // store prefetched A(it+1) -> other stage
            #pragma unroll
            for (int j = 0; j < 4; j++) {
                float4 p;
                p.x = va[j].x * vm[j].x; p.y = va[j].y * vm[j].y;
                p.z = va[j].z * vm[j].z; p.w = va[j].w * vm[j].w;
                float hx = bf_hi(p.x), hy = bf_hi(p.y), hz = bf_hi(p.z), hw = bf_hi(p.w);
                uint2 hi, lo;
                hi.x = pack_bf2(p.x, p.y);           hi.y = pack_bf2(p.z, p.w);
                lo.x = pack_bf2(p.x - hx, p.y - hy); lo.y = pack_bf2(p.z - hz, p.w - hw);
                *(uint2*)(smc + nxt + OFF_AH + aso[j]) = hi;
                *(uint2*)(smc + nxt + OFF_AL + aso[j]) = lo;
            }
            // B(it+1) via cp.async -> other stage
            const size_t bofs = (size_t)(it + 1) * BK;
            cp16(sb + nxt + OFF_BH + bso[0], pbh + bofs);
            cp16(sb + nxt + OFF_BH + bso[1], pbh + (size_t)64 * NROWS + bofs);
            cp16(sb + nxt + OFF_BL + bso[0], pbl + bofs);
            cp16(sb + nxt + OFF_BL + bso[1], pbl + (size_t)64 * NROWS + bofs);
            CP_COMMIT();
        }
        if (it + 2 < NITER) {
            const size_t aofs = (size_t)(it + 2) * BK;
            #pragma unroll
            for (int j = 0; j < 4; j++) {
                va[j] = *(const float4*)(pa + (size_t)32 * j * NROWS + aofs);
                vm[j] = *(const float4*)(pm + (size_t)32 * j * NROWS + aofs);
            }
        }

        // ---- compute from current stage ----
        const uint32_t aH = sb + cur + OFF_AH + (uint32_t)(m_base * RSTRIDE) + lane_off_A;
        const uint32_t aL = sb + cur + OFF_AL + (uint32_t)(m_base * RSTRIDE) + lane_off_A;
        const uint32_t bH = sb + cur + OFF_BH + (uint32_t)(n_base * RSTRIDE) + lane_off_B;
        const uint32_t bL = sb + cur + OFF_BL + (uint32_t)(n_base * RSTRIDE) + lane_off_B;

        #pragma unroll
        for (int ks = 0; ks < 2; ks++) {
            uint32_t ah[4][4], al[4][4], bh[4][2], bl[4][2];
            #pragma unroll
            for (int m = 0; m < 4; m++) {
                ldsm4(ah[m], aH + m * (16 * RSTRIDE) + ks * 32);
                ldsm4(al[m], aL + m * (16 * RSTRIDE) + ks * 32);
            }
            #pragma unroll
            for (int n = 0; n < 4; n++) {
                ldsm2(bh[n], bH + n * (8 * RSTRIDE) + ks * 32);
                ldsm2(bl[n], bL + n * (8 * RSTRIDE) + ks * 32);
            }
            #pragma unroll
            for (int m = 0; m < 4; m++)
                #pragma unroll
                for (int n = 0; n < 4; n++)
                    mma_bf16(acc[m][n], ah[m], bh[n]);
            #pragma unroll
            for (int m = 0; m < 4; m++)
                #pragma unroll
                for (int n = 0; n < 4; n++)
                    mma_bf16(acc[m][n], ah[m], bl[n]);
            #pragma unroll
            for (int m = 0; m < 4; m++)
                #pragma unroll
                for (int n = 0; n < 4; n++)
                    mma_bf16(acc[m][n], al[m], bh[n]);
        }

        if (it + 1 < NITER) CP_WAIT0();
        __syncthreads();
    }

    // ---------- epilogue: store partials ----------
    {
        const int g = lid >> 2;
        const int c0 = (lid & 3) * 2;
        float* base = g_part + ((size_t)blockIdx.y * NROWS + i0) * C;
        #pragma unroll
        for (int m = 0; m < 4; m++) {
            const int row0 = m_base + m * 16 + g;
            #pragma unroll
            for (int n = 0; n < 4; n++) {
                const int col = n_base + n * 8 + c0;
                float2 v0 = make_float2(acc[m][n][0], acc[m][n][1]);
                float2 v1 = make_float2(acc[m][n][2], acc[m][n][3]);
                *(float2*)(base + (size_t)row0 * C + col)       = v0;
                *(float2*)(base + (size_t)(row0 + 8) * C + col) = v1;
            }
        }
    }
}

// ============================ Kernel 3: reduce + identity ============================
__global__ void __launch_bounds__(256) k_reduce(float* __restrict__ out) {
    const size_t i = (size_t)blockIdx.x * 256 + threadIdx.x;  // float4 index
    const float4* h4 = (const float4*)g_h;
    float4 s = h4[i];
    #pragma unroll
    for (int p = 0; p < KSPLIT; p++) {
        const float4 v = ((const float4*)g_part)[(size_t)p * (NROWS * C / 4) + i];
        s.x += v.x; s.y += v.y; s.z += v.z; s.w += v.w;
    }
    ((float4*)out)[i] = s;
}

// ============================ launch ============================
extern "C" void kernel_launch(void* const* d_in, const int* in_sizes, int n_in,
                              void* d_out, int out_size) {
    const float* x    = (const float*)d_in[0];
    const float* adj  = (const float*)d_in[1];
    const float* mask = (const float*)d_in[2];
    const float* W    = (const float*)d_in[3];
    float* out = (float*)d_out;

    static int configured = 0;
    cudaFuncSetAttribute(k_spmm, cudaFuncAttributeMaxDynamicSharedMemorySize, SMEM_BYTES);
    (void)configured;

    k_linear<<<NROWS / 16, 256>>>(x, W);

    dim3 g2(NROWS / BM, KSPLIT);
    k_spmm<<<g2, THREADS, SMEM_BYTES>>>(adj, mask);

    k_reduce<<<NROWS * C / 4 / 256, 256>>>(out);
}

// round 4
// speedup vs baseline: 2.8144x; 1.2166x over previous
#include <cuda_runtime.h>
#include <cuda_bf16.h>
#include <cstdint>

#define NROWS 8192
#define C     128
#define KSPLIT 8
#define KRANGE (NROWS / KSPLIT)   // 1024
#define BK 32
#define NITER (KRANGE / BK)       // 32
#define BM 64
#define THREADS 256

#define RS_A 80                   // 32 bf16 = 64B + 16B pad
#define RS_B 272                  // 128 bf16 = 256B + 16B pad
#define TILE_A  (BM * RS_A)       // 5120
#define A_STAGE (2 * TILE_A)      // hi+lo = 10240
#define TILE_BT (BK * RS_B)       // 8704
#define B_STAGE (2 * TILE_BT)     // hi+lo = 17408
#define OFF_B0  (2 * A_STAGE)     // 20480
#define SMEM_BYTES (OFF_B0 + 3 * B_STAGE + 128)   // ~72.8KB -> 2 CTAs/SM

// ---- scratch ----
__device__ __nv_bfloat16 g_h_hi[NROWS * C];   // h row-major bf16 hi
__device__ __nv_bfloat16 g_h_lo[NROWS * C];   // h row-major bf16 lo
__device__ float g_part[KSPLIT * NROWS * C];

// ============================ helpers ============================
__device__ __forceinline__ uint32_t smem_u32(const void* p) {
    uint32_t a;
    asm("{ .reg .u64 t; cvta.to.shared.u64 t, %1; cvt.u32.u64 %0, t; }" : "=r"(a) : "l"(p));
    return a;
}
__device__ __forceinline__ void ldsm4(uint32_t* r, uint32_t addr) {
    asm volatile("ldmatrix.sync.aligned.m8n8.x4.shared.b16 {%0,%1,%2,%3}, [%4];"
                 : "=r"(r[0]), "=r"(r[1]), "=r"(r[2]), "=r"(r[3]) : "r"(addr));
}
__device__ __forceinline__ void ldsm2t(uint32_t* r, uint32_t addr) {
    asm volatile("ldmatrix.sync.aligned.m8n8.x2.trans.shared.b16 {%0,%1}, [%2];"
                 : "=r"(r[0]), "=r"(r[1]) : "r"(addr));
}
__device__ __forceinline__ void mma_bf16(float* d, const uint32_t* a, const uint32_t* b) {
    asm volatile(
        "mma.sync.aligned.m16n8k16.row.col.f32.bf16.bf16.f32 "
        "{%0,%1,%2,%3}, {%4,%5,%6,%7}, {%8,%9}, {%0,%1,%2,%3};"
        : "+f"(d[0]), "+f"(d[1]), "+f"(d[2]), "+f"(d[3])
        : "r"(a[0]), "r"(a[1]), "r"(a[2]), "r"(a[3]), "r"(b[0]), "r"(b[1]));
}
__device__ __forceinline__ void cp16(uint32_t dst, const void* src) {
    asm volatile("cp.async.cg.shared.global [%0], [%1], 16;" :: "r"(dst), "l"(src) : "memory");
}
#define CP_COMMIT() asm volatile("cp.async.commit_group;" ::: "memory")
#define CP_WAIT1()  asm volatile("cp.async.wait_group 1;" ::: "memory")

// split pair (x,y) -> packed bf16 hi + packed bf16 lo
__device__ __forceinline__ uint32_t split_pair(float x, float y, uint32_t& lo_pack) {
    __nv_bfloat162 hb = __floats2bfloat162_rn(x, y);         // .x = x (low 16)
    uint32_t hp = *reinterpret_cast<uint32_t*>(&hb);
    float hx = __uint_as_float(hp << 16);
    float hy = __uint_as_float(hp & 0xFFFF0000u);
    __nv_bfloat162 lb = __floats2bfloat162_rn(x - hx, y - hy);
    lo_pack = *reinterpret_cast<uint32_t*>(&lb);
    return hp;
}

// ============================ Kernel 1: linear, bf16 hi/lo row-major ============================
__global__ void __launch_bounds__(256) k_linear(const float* __restrict__ x,
                                                const float* __restrict__ W) {
    __shared__ float xs[16][C];
    const int tid = threadIdx.x;
    const int n0 = blockIdx.x * 16;

    #pragma unroll
    for (int i = tid; i < 16 * C / 4; i += 256) {
        int r = i >> 5, c4 = (i & 31) * 4;
        *(float4*)&xs[r][c4] = *(const float4*)(x + (size_t)(n0 + r) * C + c4);
    }
    __syncthreads();

    const int o = tid & 127, rh = tid >> 7;
    const float4* __restrict__ w4 = (const float4*)(W + (size_t)o * C);

    float acc[8];
    #pragma unroll
    for (int r = 0; r < 8; r++) acc[r] = 0.0f;

    #pragma unroll 8
    for (int c4 = 0; c4 < 32; c4++) {
        const float4 wv = w4[c4];
        #pragma unroll
        for (int r = 0; r < 8; r++) {
            const float4 xv = *(const float4*)&xs[rh * 8 + r][c4 * 4];
            acc[r] += xv.x * wv.x;
            acc[r] += xv.y * wv.y;
            acc[r] += xv.z * wv.z;
            acc[r] += xv.w * wv.w;
        }
    }

    #pragma unroll
    for (int r = 0; r < 8; r++) {
        const size_t idx = (size_t)(n0 + rh * 8 + r) * C + o;
        const float v = acc[r];
        const __nv_bfloat16 hb = __float2bfloat16_rn(v);
        const __nv_bfloat16 lb = __float2bfloat16_rn(v - __bfloat162float(hb));
        g_h_hi[idx] = hb;
        g_h_lo[idx] = lb;
    }
}

// ============================ Kernel 2: 3xbf16 mma.sync SpMM ============================
__global__ void __launch_bounds__(THREADS, 2)
k_spmm(const float* __restrict__ adj, const float* __restrict__ mask) {
    extern __shared__ char smem[];
    const uint32_t sb = (smem_u32(smem) + 127) & ~127u;

    const int tid = threadIdx.x, wid = tid >> 5, lid = tid & 31;
    const int i0 = blockIdx.x * BM;
    const int k0 = blockIdx.y * KRANGE;

    // ---- A register-prefetch mapping: 2 float4 slots (rows r0, r0+32) ----
    const int r0 = tid >> 3;             // 0..31
    const int kq = (tid & 7) * 4;        // 0..28
    const float* pa = adj  + (size_t)(i0 + r0) * NROWS + k0 + kq;
    const float* pm = mask + (size_t)(i0 + r0) * NROWS + k0 + kq;
    uint32_t aso[2];
    #pragma unroll
    for (int j = 0; j < 2; j++) aso[j] = (uint32_t)((r0 + 32 * j) * RS_A + kq * 2);

    // ---- B cp.async mapping: row=k-node, 2 chunks per tile ----
    const int brow = tid >> 3;           // 0..31
    const int bc0  = tid & 7;            // 16B chunk 0..7 (and +8)
    const __nv_bfloat16* pbh = g_h_hi + (size_t)(k0 + brow) * C + bc0 * 8;
    const __nv_bfloat16* pbl = g_h_lo + (size_t)(k0 + brow) * C + bc0 * 8;
    const uint32_t bso0 = (uint32_t)(brow * RS_B + bc0 * 16);
    const uint32_t bso1 = bso0 + 128;    // chunk +8

    // ---- warp tile: 32(m) x 32(n) ----
    const int m_base = (wid & 1) * 32;
    const int n_base = (wid >> 1) * 32;
    const uint32_t lane_off_A = (uint32_t)((lid & 15) * RS_A + ((lid >> 4) << 4));
    const uint32_t lane_off_B = (uint32_t)((lid & 15) * RS_B);

    float acc[2][4][4];
    #pragma unroll
    for (int m = 0; m < 2; m++)
        #pragma unroll
        for (int n = 0; n < 4; n++)
            #pragma unroll
            for (int q = 0; q < 4; q++) acc[m][n][q] = 0.0f;

    float4 va[2], vm[2];

    // A split+store into stage s
    auto storeA = [&](uint32_t stA) {
        #pragma unroll
        for (int j = 0; j < 2; j++) {
            float4 p;
            p.x = va[j].x * vm[j].x; p.y = va[j].y * vm[j].y;
            p.z = va[j].z * vm[j].z; p.w = va[j].w * vm[j].w;
            uint2 hi, lo;
            hi.x = split_pair(p.x, p.y, lo.x);
            hi.y = split_pair(p.z, p.w, lo.y);
            *(uint2*)(smem + (stA - smem_u32(smem)) + aso[j]) = hi;
            *(uint2*)(smem + (stA - smem_u32(smem)) + TILE_A + aso[j]) = lo;
        }
    };
    auto loadA = [&](int it) {
        const size_t ofs = (size_t)it * BK;
        #pragma unroll
        for (int j = 0; j < 2; j++) {
            va[j] = *(const float4*)(pa + (size_t)32 * j * NROWS + ofs);
            vm[j] = *(const float4*)(pm + (size_t)32 * j * NROWS + ofs);
        }
    };
    auto cpB = [&](int it, uint32_t stB) {
        const size_t ofs = (size_t)it * BK * C;
        cp16(stB + bso0, pbh + ofs);
        cp16(stB + bso1, pbh + ofs + 64);
        cp16(stB + TILE_BT + bso0, pbl + ofs);
        cp16(stB + TILE_BT + bso1, pbl + ofs + 64);
    };

    // ---------- prologue ----------
    loadA(0);
    cpB(0, sb + OFF_B0);
    CP_COMMIT();                               // G0 = B(0)
    storeA(sb);                                // A(0) -> stage 0
    loadA(1);
    cpB(1, sb + OFF_B0 + B_STAGE);
    CP_COMMIT();                               // G1 = B(1)
    CP_WAIT1();                                // B(0) done
    __syncthreads();

    int bs2 = 2;                               // (it+2) % 3
    int bsc = 0;                               // it % 3

    // ---------- mainloop ----------
    #pragma unroll 1
    for (int it = 0; it < NITER; it++) {
        // B(it+2) -> stage bs2 ; always commit (empty groups keep count uniform)
        if (it + 2 < NITER) cpB(it + 2, sb + OFF_B0 + bs2 * B_STAGE);
        CP_COMMIT();
        // A(it+1) split/store -> other A stage
        if (it + 1 < NITER) storeA(sb + ((it + 1) & 1) * A_STAGE);
        // A(it+2) -> regs
        if (it + 2 < NITER) loadA(it + 2);

        // ---- compute(it) ----
        const uint32_t aB = sb + (uint32_t)(it & 1) * A_STAGE +
                            (uint32_t)(m_base * RS_A) + lane_off_A;
        const uint32_t bB = sb + OFF_B0 + (uint32_t)bsc * B_STAGE + lane_off_B;

        #pragma unroll
        for (int ks = 0; ks < 2; ks++) {
            uint32_t ah[2][4], al[2][4], bh[4][2], bl[4][2];
            #pragma unroll
            for (int m = 0; m < 2; m++) {
                ldsm4(ah[m], aB + m * (16 * RS_A) + ks * 32);
                ldsm4(al[m], aB + TILE_A + m * (16 * RS_A) + ks * 32);
            }
            #pragma unroll
            for (int n = 0; n < 4; n++) {
                const uint32_t bo = bB + (uint32_t)(ks * 16 * RS_B) +
                                    (uint32_t)((n_base + n * 8) * 2);
                ldsm2t(bh[n], bo);
                ldsm2t(bl[n], bo + TILE_BT);
            }
            #pragma unroll
            for (int m = 0; m < 2; m++)
                #pragma unroll
                for (int n = 0; n < 4; n++)
                    mma_bf16(acc[m][n], ah[m], bh[n]);
            #pragma unroll
            for (int m = 0; m < 2; m++)
                #pragma unroll
                for (int n = 0; n < 4; n++)
                    mma_bf16(acc[m][n], ah[m], bl[n]);
            #pragma unroll
            for (int m = 0; m < 2; m++)
                #pragma unroll
                for (int n = 0; n < 4; n++)
                    mma_bf16(acc[m][n], al[m], bh[n]);
        }

        CP_WAIT1();          // B(it+1) resident for next iter
        __syncthreads();

        bs2 = (bs2 == 2) ? 0 : bs2 + 1;
        bsc = (bsc == 2) ? 0 : bsc + 1;
    }

    // ---------- epilogue ----------
    {
        const int g = lid >> 2;
        const int c0 = (lid & 3) * 2;
        float* base = g_part + ((size_t)blockIdx.y * NROWS + i0) * C;
        #pragma unroll
        for (int m = 0; m < 2; m++) {
            const int row0 = m_base + m * 16 + g;
            #pragma unroll
            for (int n = 0; n < 4; n++) {
                const int col = n_base + n * 8 + c0;
                *(float2*)(base + (size_t)row0 * C + col) =
                    make_float2(acc[m][n][0], acc[m][n][1]);
                *(float2*)(base + (size_t)(row0 + 8) * C + col) =
                    make_float2(acc[m][n][2], acc[m][n][3]);
            }
        }
    }
}

// ============================ Kernel 3: reduce + identity ============================
__global__ void __launch_bounds__(256) k_reduce(float* __restrict__ out) {
    const size_t i = (size_t)blockIdx.x * 256 + threadIdx.x;   // float4 index
    const uint2 hv = ((const uint2*)g_h_hi)[i];
    const uint2 lv = ((const uint2*)g_h_lo)[i];
    const __nv_bfloat162 h0 = *reinterpret_cast<const __nv_bfloat162*>(&hv.x);
    const __nv_bfloat162 h1 = *reinterpret_cast<const __nv_bfloat162*>(&hv.y);
    const __nv_bfloat162 l0 = *reinterpret_cast<const __nv_bfloat162*>(&lv.x);
    const __nv_bfloat162 l1 = *reinterpret_cast<const __nv_bfloat162*>(&lv.y);

    float4 s;
    s.x = __low2float(h0)  + __low2float(l0);
    s.y = __high2float(h0) + __high2float(l0);
    s.z = __low2float(h1)  + __low2float(l1);
    s.w = __high2float(h1) + __high2float(l1);

    #pragma unroll
    for (int p = 0; p < KSPLIT; p++) {
        const float4 v = ((const float4*)g_part)[(size_t)p * (NROWS * C / 4) + i];
        s.x += v.x; s.y += v.y; s.z += v.z; s.w += v.w;
    }
    ((float4*)out)[i] = s;
}

// ============================ launch ============================
extern "C" void kernel_launch(void* const* d_in, const int* in_sizes, int n_in,
                              void* d_out, int out_size) {
    const float* x    = (const float*)d_in[0];
    const float* adj  = (const float*)d_in[1];
    const float* mask = (const float*)d_in[2];
    const float* W    = (const float*)d_in[3];
    float* out = (float*)d_out;

    cudaFuncSetAttribute(k_spmm, cudaFuncAttributeMaxDynamicSharedMemorySize, SMEM_BYTES);

    k_linear<<<NROWS / 16, 256>>>(x, W);

    dim3 g2(NROWS / BM, KSPLIT);
    k_spmm<<<g2, THREADS, SMEM_BYTES>>>(adj, mask);

    k_reduce<<<NROWS * C / 4 / 256, 256>>>(out);
}

// round 5
// speedup vs baseline: 3.4947x; 1.2417x over previous
#include <cuda_runtime.h>
#include <cuda_fp16.h>
#include <cstdint>

#define NROWS 8192
#define C     128
#define KSPLIT 8
#define KRANGE (NROWS / KSPLIT)   // 1024
#define BK 32
#define NITER (KRANGE / BK)       // 32
#define BM 64
#define THREADS 256

#define RS_A 80                   // 32 fp16 = 64B + 16B pad
#define RS_B 272                  // 128 fp16 = 256B + 16B pad
#define TILE_A  (BM * RS_A)       // 5120
#define TILE_BT (BK * RS_B)       // 8704
#define OFF_B0  (2 * TILE_A)      // A double-buffered
#define SMEM_BYTES (OFF_B0 + 3 * TILE_BT + 128)   // ~36.5KB

// ---- scratch ----
__device__ float  g_h[NROWS * C];    // h fp32 row-major (for +I in reduce)
__device__ __half g_hf[NROWS * C];   // h fp16 row-major (B operand)
__device__ float  g_part[KSPLIT * NROWS * C];

// ============================ helpers ============================
__device__ __forceinline__ uint32_t smem_u32(const void* p) {
    uint32_t a;
    asm("{ .reg .u64 t; cvta.to.shared.u64 t, %1; cvt.u32.u64 %0, t; }" : "=r"(a) : "l"(p));
    return a;
}
__device__ __forceinline__ void ldsm4(uint32_t* r, uint32_t addr) {
    asm volatile("ldmatrix.sync.aligned.m8n8.x4.shared.b16 {%0,%1,%2,%3}, [%4];"
                 : "=r"(r[0]), "=r"(r[1]), "=r"(r[2]), "=r"(r[3]) : "r"(addr));
}
__device__ __forceinline__ void ldsm2t(uint32_t* r, uint32_t addr) {
    asm volatile("ldmatrix.sync.aligned.m8n8.x2.trans.shared.b16 {%0,%1}, [%2];"
                 : "=r"(r[0]), "=r"(r[1]) : "r"(addr));
}
__device__ __forceinline__ void mma_f16(float* d, const uint32_t* a, const uint32_t* b) {
    asm volatile(
        "mma.sync.aligned.m16n8k16.row.col.f32.f16.f16.f32 "
        "{%0,%1,%2,%3}, {%4,%5,%6,%7}, {%8,%9}, {%0,%1,%2,%3};"
        : "+f"(d[0]), "+f"(d[1]), "+f"(d[2]), "+f"(d[3])
        : "r"(a[0]), "r"(a[1]), "r"(a[2]), "r"(a[3]), "r"(b[0]), "r"(b[1]));
}
__device__ __forceinline__ void cp16(uint32_t dst, const void* src) {
    asm volatile("cp.async.cg.shared.global [%0], [%1], 16;" :: "r"(dst), "l"(src) : "memory");
}
#define CP_COMMIT() asm volatile("cp.async.commit_group;" ::: "memory")
#define CP_WAIT1()  asm volatile("cp.async.wait_group 1;" ::: "memory")

__device__ __forceinline__ uint32_t pack_h2(float x, float y) {
    __half2 t = __floats2half2_rn(x, y);
    return *reinterpret_cast<uint32_t*>(&t);
}

// ============================ Kernel 1: linear ============================
// Block: 32 rows of x. xs_t[c][r] transposed in smem; W fp32 in smem.
// Warp w -> outputs [w*16, w*16+16), lane -> row. Broadcast W reads.
__global__ void __launch_bounds__(256) k_linear(const float* __restrict__ x,
                                                const float* __restrict__ W) {
    __shared__ float xs_t[C][33];       // [c][row], padded
    __shared__ float Ws[C * C];         // W row-major
    const int tid = threadIdx.x;
    const int n0 = blockIdx.x * 32;

    // load x tile transposed: f over 32 c4-groups x 32 rows, lane = row
    #pragma unroll
    for (int l = 0; l < 4; l++) {
        const int f = tid + 256 * l;    // 0..1023
        const int c4 = f >> 5;          // 0..31
        const int r  = f & 31;
        const float4 v = *(const float4*)(x + (size_t)(n0 + r) * C + c4 * 4);
        xs_t[c4 * 4 + 0][r] = v.x;
        xs_t[c4 * 4 + 1][r] = v.y;
        xs_t[c4 * 4 + 2][r] = v.z;
        xs_t[c4 * 4 + 3][r] = v.w;
    }
    // load W into smem
    #pragma unroll
    for (int l = 0; l < 16; l++) {
        const int f = tid + 256 * l;    // float4 index, 0..4095
        *(float4*)&Ws[f * 4] = *(const float4*)(W + (size_t)f * 4);
    }
    __syncthreads();

    const int wid = tid >> 5, lane = tid & 31;
    const int o0 = wid * 16;

    float acc[16];
    #pragma unroll
    for (int j = 0; j < 16; j++) acc[j] = 0.0f;

    #pragma unroll 4
    for (int c4 = 0; c4 < 32; c4++) {
        float xv[4];
        #pragma unroll
        for (int i = 0; i < 4; i++) xv[i] = xs_t[c4 * 4 + i][lane];
        #pragma unroll
        for (int j = 0; j < 16; j++) {
            const float4 wv = *(const float4*)&Ws[(o0 + j) * C + c4 * 4];  // broadcast
            acc[j] += xv[0] * wv.x;
            acc[j] += xv[1] * wv.y;
            acc[j] += xv[2] * wv.z;
            acc[j] += xv[3] * wv.w;
        }
    }

    const size_t base = (size_t)(n0 + lane) * C + o0;
    #pragma unroll
    for (int j4 = 0; j4 < 4; j4++)
        *(float4*)(g_h + base + j4 * 4) =
            make_float4(acc[j4 * 4], acc[j4 * 4 + 1], acc[j4 * 4 + 2], acc[j4 * 4 + 3]);
    #pragma unroll
    for (int j8 = 0; j8 < 2; j8++) {
        uint4 pk;
        pk.x = pack_h2(acc[j8 * 8 + 0], acc[j8 * 8 + 1]);
        pk.y = pack_h2(acc[j8 * 8 + 2], acc[j8 * 8 + 3]);
        pk.z = pack_h2(acc[j8 * 8 + 4], acc[j8 * 8 + 5]);
        pk.w = pack_h2(acc[j8 * 8 + 6], acc[j8 * 8 + 7]);
        *(uint4*)(g_hf + base + j8 * 8) = pk;
    }
}

// ============================ Kernel 2: fp16 mma.sync SpMM ============================
__global__ void __launch_bounds__(THREADS, 2)
k_spmm(const float* __restrict__ adj, const float* __restrict__ mask) {
    extern __shared__ char smem[];
    const uint32_t sb = (smem_u32(smem) + 127) & ~127u;
    char* smc = smem + (sb - smem_u32(smem));

    const int tid = threadIdx.x, wid = tid >> 5, lid = tid & 31;
    const int i0 = blockIdx.x * BM;
    const int k0 = blockIdx.y * KRANGE;

    // ---- A register-prefetch: 2 float4 slots (rows r0, r0+32) ----
    const int r0 = tid >> 3;             // 0..31
    const int kq = (tid & 7) * 4;        // 0..28
    const float* pa = adj  + (size_t)(i0 + r0) * NROWS + k0 + kq;
    const float* pm = mask + (size_t)(i0 + r0) * NROWS + k0 + kq;
    uint32_t aso[2];
    #pragma unroll
    for (int j = 0; j < 2; j++) aso[j] = (uint32_t)((r0 + 32 * j) * RS_A + kq * 2);

    // ---- B cp.async: row=k-node, 2 x 16B chunks per thread ----
    const int brow = tid >> 3;           // 0..31
    const int bc0  = tid & 7;            // chunk 0..7 (and +8)
    const __half* pb = g_hf + (size_t)(k0 + brow) * C + bc0 * 8;
    const uint32_t bso0 = (uint32_t)(brow * RS_B + bc0 * 16);
    const uint32_t bso1 = bso0 + 128;

    // ---- warp tile: 32(m) x 32(n) ----
    const int m_base = (wid & 1) * 32;
    const int n_base = (wid >> 1) * 32;
    const uint32_t lane_off_A = (uint32_t)((lid & 15) * RS_A + ((lid >> 4) << 4));
    const uint32_t lane_off_B = (uint32_t)((lid & 15) * RS_B);

    float acc[2][4][4];
    #pragma unroll
    for (int m = 0; m < 2; m++)
        #pragma unroll
        for (int n = 0; n < 4; n++)
            #pragma unroll
            for (int q = 0; q < 4; q++) acc[m][n][q] = 0.0f;

    float4 va[2], vm[2];

    auto storeA = [&](int stage) {
        char* dst = smc + stage * TILE_A;
        #pragma unroll
        for (int j = 0; j < 2; j++) {
            float4 p;
            p.x = va[j].x * vm[j].x; p.y = va[j].y * vm[j].y;
            p.z = va[j].z * vm[j].z; p.w = va[j].w * vm[j].w;
            uint2 h;
            h.x = pack_h2(p.x, p.y);
            h.y = pack_h2(p.z, p.w);
            *(uint2*)(dst + aso[j]) = h;
        }
    };
    auto loadA = [&](int it) {
        const size_t ofs = (size_t)it * BK;
        #pragma unroll
        for (int j = 0; j < 2; j++) {
            va[j] = *(const float4*)(pa + (size_t)32 * j * NROWS + ofs);
            vm[j] = *(const float4*)(pm + (size_t)32 * j * NROWS + ofs);
        }
    };
    auto cpB = [&](int it, int stage) {
        const uint32_t stB = sb + OFF_B0 + (uint32_t)stage * TILE_BT;
        const size_t ofs = (size_t)it * BK * C;
        cp16(stB + bso0, pb + ofs);
        cp16(stB + bso1, pb + ofs + 64);
    };

    // ---------- prologue ----------
    loadA(0);
    cpB(0, 0); CP_COMMIT();
    storeA(0);
    loadA(1);
    cpB(1, 1); CP_COMMIT();
    CP_WAIT1();
    __syncthreads();

    int bs2 = 2, bsc = 0;

    // ---------- mainloop ----------
    #pragma unroll 1
    for (int it = 0; it < NITER; it++) {
        if (it + 2 < NITER) cpB(it + 2, bs2);
        CP_COMMIT();
        if (it + 1 < NITER) storeA((it + 1) & 1);
        if (it + 2 < NITER) loadA(it + 2);

        const uint32_t aB = sb + (uint32_t)(it & 1) * TILE_A +
                            (uint32_t)(m_base * RS_A) + lane_off_A;
        const uint32_t bB = sb + OFF_B0 + (uint32_t)bsc * TILE_BT + lane_off_B;

        #pragma unroll
        for (int ks = 0; ks < 2; ks++) {
            uint32_t ah[2][4], bh[4][2];
            #pragma unroll
            for (int m = 0; m < 2; m++)
                ldsm4(ah[m], aB + m * (16 * RS_A) + ks * 32);
            #pragma unroll
            for (int n = 0; n < 4; n++)
                ldsm2t(bh[n], bB + (uint32_t)(ks * 16 * RS_B) +
                              (uint32_t)((n_base + n * 8) * 2));
            #pragma unroll
            for (int m = 0; m < 2; m++)
                #pragma unroll
                for (int n = 0; n < 4; n++)
                    mma_f16(acc[m][n], ah[m], bh[n]);
        }

        CP_WAIT1();
        __syncthreads();

        bs2 = (bs2 == 2) ? 0 : bs2 + 1;
        bsc = (bsc == 2) ? 0 : bsc + 1;
    }

    // ---------- epilogue ----------
    {
        const int g = lid >> 2;
        const int c0 = (lid & 3) * 2;
        float* base = g_part + ((size_t)blockIdx.y * NROWS + i0) * C;
        #pragma unroll
        for (int m = 0; m < 2; m++) {
            const int row0 = m_base + m * 16 + g;
            #pragma unroll
            for (int n = 0; n < 4; n++) {
                const int col = n_base + n * 8 + c0;
                *(float2*)(base + (size_t)row0 * C + col) =
                    make_float2(acc[m][n][0], acc[m][n][1]);
                *(float2*)(base + (size_t)(row0 + 8) * C + col) =
                    make_float2(acc[m][n][2], acc[m][n][3]);
            }
        }
    }
}

// ============================ Kernel 3: reduce + identity ============================
__global__ void __launch_bounds__(256) k_reduce(float* __restrict__ out) {
    const size_t i = (size_t)blockIdx.x * 256 + threadIdx.x;   // float4 index
    float4 s = ((const float4*)g_h)[i];
    #pragma unroll
    for (int p = 0; p < KSPLIT; p++) {
        const float4 v = ((const float4*)g_part)[(size_t)p * (NROWS * C / 4) + i];
        s.x += v.x; s.y += v.y; s.z += v.z; s.w += v.w;
    }
    ((float4*)out)[i] = s;
}

// ============================ launch ============================
extern "C" void kernel_launch(void* const* d_in, const int* in_sizes, int n_in,
                              void* d_out, int out_size) {
    const float* x    = (const float*)d_in[0];
    const float* adj  = (const float*)d_in[1];
    const float* mask = (const float*)d_in[2];
    const float* W    = (const float*)d_in[3];
    float* out = (float*)d_out;

    cudaFuncSetAttribute(k_spmm, cudaFuncAttributeMaxDynamicSharedMemorySize, SMEM_BYTES);

    k_linear<<<NROWS / 32, 256>>>(x, W);

    dim3 g2(NROWS / BM, KSPLIT);
    k_spmm<<<g2, THREADS, SMEM_BYTES>>>(adj, mask);

    k_reduce<<<NROWS * C / 4 / 256, 256>>>(out);
}

// round 6
// speedup vs baseline: 4.0105x; 1.1476x over previous
#include <cuda_runtime.h>
#include <cuda_fp16.h>
#include <cstdint>

#define NROWS 8192
#define C     128
#define KSPLIT 8
#define KRANGE (NROWS / KSPLIT)   // 1024
#define BK 64
#define NITER (KRANGE / BK)       // 16
#define BM 64
#define THREADS 256

#define RS_A 144                  // 64 fp16 = 128B + 16B pad
#define RS_B 272                  // 128 fp16 = 256B + 16B pad
#define TILE_A  (BM * RS_A)       // 9216
#define TILE_BT (BK * RS_B)       // 17408
#define OFF_B0  (2 * TILE_A)      // 18432
#define SMEM_BYTES (OFF_B0 + 3 * TILE_BT + 128)   // ~70.8KB -> 2 CTAs/SM

// k_linear smem
#define LRS 272                   // 128 fp16 + 16B pad
#define L_TILE_X (64 * LRS)       // 17408
#define L_SMEM (L_TILE_X + 128 * LRS + 128)       // ~52.4KB

// ---- scratch ----
__device__ float  g_h[NROWS * C];    // h fp32 row-major (for +I in reduce)
__device__ __half g_hf[NROWS * C];   // h fp16 row-major (B operand)
__device__ float  g_part[KSPLIT * NROWS * C];

// ============================ helpers ============================
__device__ __forceinline__ uint32_t smem_u32(const void* p) {
    uint32_t a;
    asm("{ .reg .u64 t; cvta.to.shared.u64 t, %1; cvt.u32.u64 %0, t; }" : "=r"(a) : "l"(p));
    return a;
}
__device__ __forceinline__ void ldsm4(uint32_t* r, uint32_t addr) {
    asm volatile("ldmatrix.sync.aligned.m8n8.x4.shared.b16 {%0,%1,%2,%3}, [%4];"
                 : "=r"(r[0]), "=r"(r[1]), "=r"(r[2]), "=r"(r[3]) : "r"(addr));
}
__device__ __forceinline__ void ldsm2(uint32_t* r, uint32_t addr) {
    asm volatile("ldmatrix.sync.aligned.m8n8.x2.shared.b16 {%0,%1}, [%2];"
                 : "=r"(r[0]), "=r"(r[1]) : "r"(addr));
}
__device__ __forceinline__ void ldsm2t(uint32_t* r, uint32_t addr) {
    asm volatile("ldmatrix.sync.aligned.m8n8.x2.trans.shared.b16 {%0,%1}, [%2];"
                 : "=r"(r[0]), "=r"(r[1]) : "r"(addr));
}
__device__ __forceinline__ void mma_f16(float* d, const uint32_t* a, const uint32_t* b) {
    asm volatile(
        "mma.sync.aligned.m16n8k16.row.col.f32.f16.f16.f32 "
        "{%0,%1,%2,%3}, {%4,%5,%6,%7}, {%8,%9}, {%0,%1,%2,%3};"
        : "+f"(d[0]), "+f"(d[1]), "+f"(d[2]), "+f"(d[3])
        : "r"(a[0]), "r"(a[1]), "r"(a[2]), "r"(a[3]), "r"(b[0]), "r"(b[1]));
}
__device__ __forceinline__ void cp16(uint32_t dst, const void* src) {
    asm volatile("cp.async.cg.shared.global [%0], [%1], 16;" :: "r"(dst), "l"(src) : "memory");
}
#define CP_COMMIT() asm volatile("cp.async.commit_group;" ::: "memory")
#define CP_WAIT1()  asm volatile("cp.async.wait_group 1;" ::: "memory")

__device__ __forceinline__ uint32_t pack_h2(float x, float y) {
    __half2 t = __floats2half2_rn(x, y);
    return *reinterpret_cast<uint32_t*>(&t);
}
__device__ __forceinline__ void sts128u(uint32_t addr, uint4 v) {
    asm volatile("st.shared.v4.b32 [%0], {%1,%2,%3,%4};"
                 :: "r"(addr), "r"(v.x), "r"(v.y), "r"(v.z), "r"(v.w) : "memory");
}

// ============================ Kernel 1: linear via fp16 mma ============================
// CTA: 64 rows x full n=128. 8 warps: wm = wid>>1 (m16 each), wn = wid&1 (n64 each).
__global__ void __launch_bounds__(256) k_linear(const float* __restrict__ x,
                                                const float* __restrict__ W) {
    extern __shared__ char lsm[];
    const uint32_t sb = smem_u32(lsm);
    const uint32_t xa = sb;                 // 64 x LRS
    const uint32_t Ws = sb + L_TILE_X;      // 128 x LRS
    const int tid = threadIdx.x;
    const int n0 = blockIdx.x * 64;

    // x -> fp16 smem
    #pragma unroll
    for (int l = 0; l < 8; l++) {
        const int f = tid + 256 * l;        // 0..2047
        const int r = f >> 5, c4 = f & 31;
        const float4 v = *(const float4*)(x + (size_t)(n0 + r) * C + c4 * 4);
        uint2 pk; pk.x = pack_h2(v.x, v.y); pk.y = pack_h2(v.z, v.w);
        *(uint2*)(lsm + r * LRS + c4 * 8) = pk;
    }
    // W -> fp16 smem
    #pragma unroll
    for (int l = 0; l < 16; l++) {
        const int f = tid + 256 * l;        // 0..4095
        const int r = f >> 5, c4 = f & 31;
        const float4 v = *(const float4*)(W + (size_t)r * C + c4 * 4);
        uint2 pk; pk.x = pack_h2(v.x, v.y); pk.y = pack_h2(v.z, v.w);
        *(uint2*)(lsm + L_TILE_X + r * LRS + c4 * 8) = pk;
    }
    __syncthreads();

    const int wid = tid >> 5, lid = tid & 31;
    const int wm = wid >> 1, wn = wid & 1;

    const uint32_t aBase = xa + (uint32_t)(wm * 16) * LRS +
                           (uint32_t)((lid & 15) * LRS + ((lid >> 4) << 4));
    const uint32_t bBase = Ws + (uint32_t)((wn * 64 + (lid & 7)) * LRS +
                           (((lid >> 3) & 1) << 4));

    float acc[8][4];
    #pragma unroll
    for (int n = 0; n < 8; n++)
        #pragma unroll
        for (int q = 0; q < 4; q++) acc[n][q] = 0.0f;

    #pragma unroll
    for (int ks = 0; ks < 8; ks++) {
        uint32_t a[4], b[8][2];
        ldsm4(a, aBase + ks * 32);
        #pragma unroll
        for (int n = 0; n < 8; n++)
            ldsm2(b[n], bBase + (uint32_t)(n * 8) * LRS + ks * 32);
        #pragma unroll
        for (int n = 0; n < 8; n++)
            mma_f16(acc[n], a, b[n]);
    }

    // epilogue: fp32 g_h + fp16 g_hf
    const int g = lid >> 2;
    const int c0 = (lid & 3) * 2;
    #pragma unroll
    for (int half = 0; half < 2; half++) {
        const int row = n0 + wm * 16 + g + half * 8;
        #pragma unroll
        for (int n = 0; n < 8; n++) {
            const int col = wn * 64 + n * 8 + c0;
            const float vx = acc[n][half * 2 + 0];
            const float vy = acc[n][half * 2 + 1];
            *(float2*)(g_h + (size_t)row * C + col) = make_float2(vx, vy);
            *(uint32_t*)(g_hf + (size_t)row * C + col) = pack_h2(vx, vy);
        }
    }
}

// ============================ Kernel 2: fp16 mma.sync SpMM, BK=64 ============================
__global__ void __launch_bounds__(THREADS, 2)
k_spmm(const float* __restrict__ adj, const float* __restrict__ mask) {
    extern __shared__ char smem[];
    const uint32_t sb = (smem_u32(smem) + 127) & ~127u;

    const int tid = threadIdx.x, wid = tid >> 5, lid = tid & 31;
    const int i0 = blockIdx.x * BM;
    const int k0 = blockIdx.y * KRANGE;

    // ---- A: row = tid>>2 (0..63), kq = (tid&3)*16 floats, 4 float4 each ----
    const int r0 = tid >> 2;
    const int kq = (tid & 3) * 16;
    const float* pa = adj  + (size_t)(i0 + r0) * NROWS + k0 + kq;
    const float* pm = mask + (size_t)(i0 + r0) * NROWS + k0 + kq;
    const uint32_t asoB = (uint32_t)(r0 * RS_A + (tid & 3) * 32);   // bytes

    // ---- B cp.async: brow = tid>>2 (0..63), chunks at (tid&3)*32B + {0,16,128,144} ----
    const int brow = tid >> 2;
    const __half* pb = g_hf + (size_t)(k0 + brow) * C + (tid & 3) * 16;
    const uint32_t bsoB = (uint32_t)(brow * RS_B + (tid & 3) * 32);

    // ---- warp tile: 32(m) x 32(n) ----
    const int m_base = (wid & 1) * 32;
    const int n_base = (wid >> 1) * 32;
    const uint32_t lane_off_A = (uint32_t)((lid & 15) * RS_A + ((lid >> 4) << 4));
    const uint32_t lane_off_B = (uint32_t)((lid & 15) * RS_B);

    float acc[2][4][4];
    #pragma unroll
    for (int m = 0; m < 2; m++)
        #pragma unroll
        for (int n = 0; n < 4; n++)
            #pragma unroll
            for (int q = 0; q < 4; q++) acc[m][n][q] = 0.0f;

    float4 va[4], vm[4];

    auto loadA = [&](int it) {
        const size_t ofs = (size_t)it * BK;
        #pragma unroll
        for (int j = 0; j < 4; j++) {
            va[j] = *(const float4*)(pa + ofs + j * 4);
            vm[j] = *(const float4*)(pm + ofs + j * 4);
        }
    };
    auto storeA = [&](int stage) {
        const uint32_t dst = sb + (uint32_t)stage * TILE_A + asoB;
        uint4 w0, w1;
        {
            float4 p0, p1;
            p0.x = va[0].x * vm[0].x; p0.y = va[0].y * vm[0].y;
            p0.z = va[0].z * vm[0].z; p0.w = va[0].w * vm[0].w;
            p1.x = va[1].x * vm[1].x; p1.y = va[1].y * vm[1].y;
            p1.z = va[1].z * vm[1].z; p1.w = va[1].w * vm[1].w;
            w0.x = pack_h2(p0.x, p0.y); w0.y = pack_h2(p0.z, p0.w);
            w0.z = pack_h2(p1.x, p1.y); w0.w = pack_h2(p1.z, p1.w);
        }
        {
            float4 p0, p1;
            p0.x = va[2].x * vm[2].x; p0.y = va[2].y * vm[2].y;
            p0.z = va[2].z * vm[2].z; p0.w = va[2].w * vm[2].w;
            p1.x = va[3].x * vm[3].x; p1.y = va[3].y * vm[3].y;
            p1.z = va[3].z * vm[3].z; p1.w = va[3].w * vm[3].w;
            w1.x = pack_h2(p0.x, p0.y); w1.y = pack_h2(p0.z, p0.w);
            w1.z = pack_h2(p1.x, p1.y); w1.w = pack_h2(p1.z, p1.w);
        }
        sts128u(dst, w0);
        sts128u(dst + 16, w1);
    };
    auto cpB = [&](int it, int stage) {
        const uint32_t stB = sb + OFF_B0 + (uint32_t)stage * TILE_BT + bsoB;
        const __half* src = pb + (size_t)it * BK * C;
        cp16(stB,       src);
        cp16(stB + 16,  src + 8);
        cp16(stB + 128, src + 64);
        cp16(stB + 144, src + 72);
    };

    // ---------- prologue ----------
    loadA(0);
    cpB(0, 0); CP_COMMIT();
    storeA(0);
    loadA(1);
    cpB(1, 1); CP_COMMIT();
    CP_WAIT1();
    __syncthreads();

    int bs2 = 2, bsc = 0;

    // ---------- mainloop ----------
    #pragma unroll 1
    for (int it = 0; it < NITER; it++) {
        if (it + 2 < NITER) cpB(it + 2, bs2);
        CP_COMMIT();
        if (it + 1 < NITER) storeA((it + 1) & 1);
        if (it + 2 < NITER) loadA(it + 2);

        const uint32_t aB = sb + (uint32_t)(it & 1) * TILE_A +
                            (uint32_t)(m_base * RS_A) + lane_off_A;
        const uint32_t bB = sb + OFF_B0 + (uint32_t)bsc * TILE_BT + lane_off_B;

        #pragma unroll
        for (int ks = 0; ks < 4; ks++) {
            uint32_t ah[2][4], bh[4][2];
            #pragma unroll
            for (int m = 0; m < 2; m++)
                ldsm4(ah[m], aB + m * (16 * RS_A) + ks * 32);
            #pragma unroll
            for (int n = 0; n < 4; n++)
                ldsm2t(bh[n], bB + (uint32_t)(ks * 16 * RS_B) +
                              (uint32_t)((n_base + n * 8) * 2));
            #pragma unroll
            for (int m = 0; m < 2; m++)
                #pragma unroll
                for (int n = 0; n < 4; n++)
                    mma_f16(acc[m][n], ah[m], bh[n]);
        }

        CP_WAIT1();
        __syncthreads();

        bs2 = (bs2 == 2) ? 0 : bs2 + 1;
        bsc = (bsc == 2) ? 0 : bsc + 1;
    }

    // ---------- epilogue ----------
    {
        const int g = lid >> 2;
        const int c0 = (lid & 3) * 2;
        float* base = g_part + ((size_t)blockIdx.y * NROWS + i0) * C;
        #pragma unroll
        for (int m = 0; m < 2; m++) {
            const int row0 = m_base + m * 16 + g;
            #pragma unroll
            for (int n = 0; n < 4; n++) {
                const int col = n_base + n * 8 + c0;
                *(float2*)(base + (size_t)row0 * C + col) =
                    make_float2(acc[m][n][0], acc[m][n][1]);
                *(float2*)(base + (size_t)(row0 + 8) * C + col) =
                    make_float2(acc[m][n][2], acc[m][n][3]);
            }
        }
    }
}

// ============================ Kernel 3: reduce + identity ============================
__global__ void __launch_bounds__(256) k_reduce(float* __restrict__ out) {
    const size_t i = (size_t)blockIdx.x * 256 + threadIdx.x;   // float4 index
    float4 s = ((const float4*)g_h)[i];
    #pragma unroll
    for (int p = 0; p < KSPLIT; p++) {
        const float4 v = ((const float4*)g_part)[(size_t)p * (NROWS * C / 4) + i];
        s.x += v.x; s.y += v.y; s.z += v.z; s.w += v.w;
    }
    ((float4*)out)[i] = s;
}

// ============================ launch ============================
extern "C" void kernel_launch(void* const* d_in, const int* in_sizes, int n_in,
                              void* d_out, int out_size) {
    const float* x    = (const float*)d_in[0];
    const float* adj  = (const float*)d_in[1];
    const float* mask = (const float*)d_in[2];
    const float* W    = (const float*)d_in[3];
    float* out = (float*)d_out;

    cudaFuncSetAttribute(k_spmm, cudaFuncAttributeMaxDynamicSharedMemorySize, SMEM_BYTES);
    cudaFuncSetAttribute(k_linear, cudaFuncAttributeMaxDynamicSharedMemorySize, L_SMEM);

    k_linear<<<NROWS / 64, 256, L_SMEM>>>(x, W);

    dim3 g2(NROWS / BM, KSPLIT);
    k_spmm<<<g2, THREADS, SMEM_BYTES>>>(adj, mask);

    k_reduce<<<NROWS * C / 4 / 256, 256>>>(out);
}